// round 12
// baseline (speedup 1.0000x reference)
#include <cuda_runtime.h>
#include <math.h>

#define LAMDA 0.1f
#define T_AVG 8192
#define THREADS 512
#define T8 (T_AVG / 8)              // 1024 float8 per "row"
#define STRIPES (T8 / THREADS)      // 2 column stripes
#define SLABS 148                   // row-pair slabs
#define BLOCKS (STRIPES * SLABS)    // 296 = 2 CTAs/SM, single wave

// Accumulators: zero at module load; reset by the last block each launch,
// so every graph replay starts clean. Counter self-wraps via atomicInc.
__device__ float g_acc0;
__device__ float g_acc1;
__device__ unsigned int g_count;

struct F8 { float4 lo, hi; };

__device__ __forceinline__ F8 unpack(unsigned long long x0, unsigned long long x1,
                                     unsigned long long x2, unsigned long long x3) {
    F8 r;
    r.lo.x = __uint_as_float((unsigned)x0);
    r.lo.y = __uint_as_float((unsigned)(x0 >> 32));
    r.lo.z = __uint_as_float((unsigned)x1);
    r.lo.w = __uint_as_float((unsigned)(x1 >> 32));
    r.hi.x = __uint_as_float((unsigned)x2);
    r.hi.y = __uint_as_float((unsigned)(x2 >> 32));
    r.hi.z = __uint_as_float((unsigned)x3);
    r.hi.w = __uint_as_float((unsigned)(x3 >> 32));
    return r;
}

// `in` loads: pin in L2 (evict_last) so the array stays resident across graph
// replays. `tg` loads: evict_first so the streaming target never displaces it.
// sm_103 requires .v4.b64 (256-bit) for L2 evict hints.
__device__ __forceinline__ F8 ld_keep(const F8* p) {
    unsigned long long x0, x1, x2, x3;
    asm("ld.global.nc.L2::evict_last.v4.b64 {%0,%1,%2,%3}, [%4];"
        : "=l"(x0), "=l"(x1), "=l"(x2), "=l"(x3) : "l"(p));
    return unpack(x0, x1, x2, x3);
}
__device__ __forceinline__ F8 ld_stream(const F8* p) {
    unsigned long long x0, x1, x2, x3;
    asm("ld.global.nc.L2::evict_first.v4.b64 {%0,%1,%2,%3}, [%4];"
        : "=l"(x0), "=l"(x1), "=l"(x2), "=l"(x3) : "l"(p));
    return unpack(x0, x1, x2, x3);
}

__device__ __forceinline__ float sq4(float4 a, float4 b) {
    float d0 = a.x - b.x;
    float d1 = a.y - b.y;
    float d2 = a.z - b.z;
    float d3 = a.w - b.w;
    return d0 * d0 + d1 * d1 + d2 * d2 + d3 * d3;
}
__device__ __forceinline__ float sq8(F8 a, F8 b) {
    return sq4(a.lo, b.lo) + sq4(a.hi, b.hi);
}

// View in/tg as [nRows x T8] float8. Thread owns one column; walks row-pairs.
// Pair p covers rows (2p, 2p+1): mse for both rows, cyc diff (2p,2p+1) direct,
// cyc diff (2p-1,2p) via carried previous row (direct boundary load for the
// slab's first pair). Every `in` element is loaded ONCE (+1 row per slab).
__global__ void __launch_bounds__(THREADS, 2) fused_loss_kernel(
    const F8* __restrict__ in,
    const F8* __restrict__ tg,
    float* __restrict__ out,
    int nRows, int pairsPerSlab,
    float inv_n, int nSteps)
{
    float s_mse = 0.0f;
    float s_cyc = 0.0f;

    const int stripe = blockIdx.x % STRIPES;
    const int slab = blockIdx.x / STRIPES;
    const int col = stripe * THREADS + threadIdx.x;
    const int totalPairs = nRows >> 1;

    int p0 = slab * pairsPerSlab;
    int p1 = min(p0 + pairsPerSlab, totalPairs);

    if (p0 < p1) {
        const F8* ip = in + col;
        const F8* tp = tg + col;
        int off = 2 * p0 * T8;

        F8 carry;
        // Slab-boundary diff (2p0-1, 2p0): direct load of the previous row.
        if (p0 > 0) {
            carry = ld_keep(&ip[off - T8]);
        }

        // First pair (peeled: carry diff conditional on p0>0).
        {
            F8 a0 = ld_keep(&ip[off]);
            F8 a1 = ld_keep(&ip[off + T8]);
            F8 b0 = ld_stream(&tp[off]);
            F8 b1 = ld_stream(&tp[off + T8]);
            s_mse += sq8(a0, b0);
            s_mse += sq8(a1, b1);
            s_cyc += sq8(a0, a1);
            if (p0 > 0) s_cyc += sq8(carry, a0);
            carry = a1;
            off += 2 * T8;
        }

        // Main pair loop: 4 front-batched 32B LDG.256 per iteration.
        for (int p = p0 + 1; p < p1; p++, off += 2 * T8) {
            F8 a0 = ld_keep(&ip[off]);
            F8 a1 = ld_keep(&ip[off + T8]);
            F8 b0 = ld_stream(&tp[off]);
            F8 b1 = ld_stream(&tp[off + T8]);
            s_mse += sq8(a0, b0);
            s_mse += sq8(a1, b1);
            s_cyc += sq8(carry, a0);   // (2p-1, 2p)
            s_cyc += sq8(a0, a1);      // (2p, 2p+1)
            carry = a1;
        }

        // Generic safety: odd trailing row (not hit for nRows=2048).
        if ((nRows & 1) && p1 == totalPairs) {
            int r = nRows - 1;
            F8 a = ld_keep(&ip[r * T8]);
            F8 b = ld_stream(&tp[r * T8]);
            s_mse += sq8(a, b);
            s_cyc += sq8(carry, a);   // carry == row nRows-2
        }
    }

    // Warp reduction
    #pragma unroll
    for (int off = 16; off > 0; off >>= 1) {
        s_mse += __shfl_xor_sync(0xffffffffu, s_mse, off);
        s_cyc += __shfl_xor_sync(0xffffffffu, s_cyc, off);
    }

    __shared__ float sm_mse[THREADS / 32];
    __shared__ float sm_cyc[THREADS / 32];
    int wid = threadIdx.x >> 5;
    int lid = threadIdx.x & 31;
    if (lid == 0) {
        sm_mse[wid] = s_mse;
        sm_cyc[wid] = s_cyc;
    }
    __syncthreads();

    if (threadIdx.x == 0) {
        float bm = sm_mse[0];
        float bc = sm_cyc[0];
        #pragma unroll
        for (int w = 1; w < THREADS / 32; w++) {
            bm += sm_mse[w];
            bc += sm_cyc[w];
        }
        atomicAdd(&g_acc0, bm);
        atomicAdd(&g_acc1, bc);
        __threadfence();
        // atomicInc wraps to 0 when old == gridDim.x-1 -> self-resetting counter
        unsigned int ticket = atomicInc(&g_count, gridDim.x - 1);
        if (ticket == gridDim.x - 1) {
            float tot_mse = atomicAdd(&g_acc0, 0.0f);
            float tot_cyc = atomicAdd(&g_acc1, 0.0f);
            float l1 = (nSteps != 1) ? (LAMDA * sqrtf(tot_cyc)) : 0.0f;
            out[0] = tot_mse * inv_n + l1;
            // Reset for next graph replay.
            g_acc0 = 0.0f;
            g_acc1 = 0.0f;
        }
    }
}

extern "C" void kernel_launch(void* const* d_in, const int* in_sizes, int n_in,
                              void* d_out, int out_size) {
    const float* input  = (const float*)d_in[0];
    const float* target = (const float*)d_in[1];
    float* out = (float*)d_out;

    int n = in_sizes[0];         // 16,777,216
    int n8 = n / 8;
    int T = T_AVG;               // 8192 (fixed for this problem)
    int nSteps = n / T;          // 2048
    int nRows = n8 / T8;         // 2048 rows of T8 float8
    int totalPairs = nRows / 2;  // 1024
    int pairsPerSlab = (totalPairs + SLABS - 1) / SLABS;  // 7

    fused_loss_kernel<<<BLOCKS, THREADS>>>(
        (const F8*)input, (const F8*)target, out,
        nRows, pairsPerSlab, 1.0f / (float)n, nSteps);
}